// round 1
// baseline (speedup 1.0000x reference)
#include <cuda_runtime.h>
#include <math.h>

// Problem constants
#define T_STEPS 50
#define BATCH   1024
#define NPD     512
#define NHD     512
#define NGD     4096
#define CHUNK   10          // decode every 10 steps

// Scratch (device globals per harness rules: no cudaMalloc anywhere)
__device__ float d_hx[2][BATCH * NHD];
__device__ float d_cx[2][BATCH * NHD];
__device__ float d_gbuf[CHUNK][(size_t)BATCH * NGD];   // 10*1024*4096*4 = 168 MB

// ---------------------------------------------------------------------------
// Generic fp32 GEMM: C[m,n] = sum_k A[m,k] * W[n,k]  (+bias[n])  (optional ReLU)
// A: [M,K] row-major, W: [N,K] row-major (i.e. C = A @ W^T)
// Tile: BM=128, BN=128, BK=16, 256 threads, 8x8 per thread.
// M % 128 == 0, N % 128 == 0, K % 16 == 0 (true for all shapes here).
// ---------------------------------------------------------------------------
template <bool RELU>
__global__ __launch_bounds__(256)
void gemm_bt(const float* __restrict__ A, const float* __restrict__ W,
             const float* __restrict__ bias, float* __restrict__ C,
             int M, int N, int K)
{
    __shared__ float As[16][132];
    __shared__ float Ws[16][132];

    const int tid = threadIdx.x;
    const int tn  = tid & 15;        // 0..15 -> 8 cols each
    const int tm  = tid >> 4;        // 0..15 -> 8 rows each
    const int m0  = blockIdx.y << 7;
    const int n0  = blockIdx.x << 7;

    const int lr = tid >> 2;         // 0..63
    const int lk = (tid & 3) << 2;   // 0,4,8,12

    float acc[8][8];
#pragma unroll
    for (int i = 0; i < 8; i++)
#pragma unroll
        for (int j = 0; j < 8; j++) acc[i][j] = 0.f;

    const float* Ap = A + (size_t)(m0 + lr) * K + lk;
    const float* Wp = W + (size_t)(n0 + lr) * K + lk;
    const size_t strideA = (size_t)64 * K;

    for (int k0 = 0; k0 < K; k0 += 16) {
        float4 a0 = *(const float4*)(Ap + k0);
        float4 a1 = *(const float4*)(Ap + strideA + k0);
        float4 w0 = *(const float4*)(Wp + k0);
        float4 w1 = *(const float4*)(Wp + strideA + k0);

        __syncthreads();
        As[lk + 0][lr]      = a0.x; As[lk + 1][lr]      = a0.y;
        As[lk + 2][lr]      = a0.z; As[lk + 3][lr]      = a0.w;
        As[lk + 0][lr + 64] = a1.x; As[lk + 1][lr + 64] = a1.y;
        As[lk + 2][lr + 64] = a1.z; As[lk + 3][lr + 64] = a1.w;
        Ws[lk + 0][lr]      = w0.x; Ws[lk + 1][lr]      = w0.y;
        Ws[lk + 2][lr]      = w0.z; Ws[lk + 3][lr]      = w0.w;
        Ws[lk + 0][lr + 64] = w1.x; Ws[lk + 1][lr + 64] = w1.y;
        Ws[lk + 2][lr + 64] = w1.z; Ws[lk + 3][lr + 64] = w1.w;
        __syncthreads();

#pragma unroll
        for (int kk = 0; kk < 16; kk++) {
            float av[8], wv[8];
            *(float4*)(av)     = *(const float4*)&As[kk][tm * 8];
            *(float4*)(av + 4) = *(const float4*)&As[kk][tm * 8 + 4];
            *(float4*)(wv)     = *(const float4*)&Ws[kk][tn * 8];
            *(float4*)(wv + 4) = *(const float4*)&Ws[kk][tn * 8 + 4];
#pragma unroll
            for (int i = 0; i < 8; i++)
#pragma unroll
                for (int j = 0; j < 8; j++)
                    acc[i][j] = fmaf(av[i], wv[j], acc[i][j]);
        }
    }

#pragma unroll
    for (int j = 0; j < 8; j++) {
        const int col = n0 + tn * 8 + j;
        const float bb = bias ? bias[col] : 0.f;
#pragma unroll
        for (int i = 0; i < 8; i++) {
            const int row = m0 + tm * 8 + i;
            float v = acc[i][j] + bb;
            if (RELU) v = fmaxf(v, 0.f);
            C[(size_t)row * N + col] = v;
        }
    }
}

// ---------------------------------------------------------------------------
// Fused LSTM step: gates GEMM (hx @ w_hh^T) + rank-2 input term + biases +
// sigmoid/tanh elementwise + cell/hidden update, all in one kernel.
// Block tile: 128 batch rows x 32 hidden cols x all 4 gates (eff. BN=128).
// Thread (tn,tm): 8 rows x 2 cols x 4 gates. Grid: (NH/32, B/128) = (16, 8).
// Effective col index jj = g*2 + c  maps to w_hh row  g*NH + nh0 + tn*2 + c.
// ---------------------------------------------------------------------------
__global__ __launch_bounds__(256)
void lstm_step(const float* __restrict__ hx_in, const float* __restrict__ cx_in,
               float* __restrict__ hx_out, float* __restrict__ cx_out,
               const float* __restrict__ v,
               const float* __restrict__ w_hh, const float* __restrict__ w_ih,
               const float* __restrict__ b_ih, const float* __restrict__ b_hh,
               int t)
{
    __shared__ float As[16][132];
    __shared__ float Ws[16][132];

    const int tid = threadIdx.x;
    const int tn  = tid & 15;
    const int tm  = tid >> 4;
    const int m0  = blockIdx.y << 7;      // batch block
    const int nh0 = blockIdx.x << 5;      // 32 hidden cols

    const int lr = tid >> 2;              // 0..63
    const int lk = (tid & 3) << 2;        // 0,4,8,12

    float acc[8][8];                      // [row][g*2 + c]
#pragma unroll
    for (int i = 0; i < 8; i++)
#pragma unroll
        for (int j = 0; j < 8; j++) acc[i][j] = 0.f;

    // w_hh rows for the two eff-cols this thread's loader handles
    const int j0   = lr;
    const int j1   = lr + 64;
    const int wr0  = (j0 >> 5) * NHD + nh0 + (j0 & 31);
    const int wr1  = (j1 >> 5) * NHD + nh0 + (j1 & 31);
    const float* Ap  = hx_in + (size_t)(m0 + lr) * NHD + lk;
    const float* Wp0 = w_hh + (size_t)wr0 * NHD + lk;
    const float* Wp1 = w_hh + (size_t)wr1 * NHD + lk;

    for (int k0 = 0; k0 < NHD; k0 += 16) {
        float4 a0 = *(const float4*)(Ap + k0);
        float4 a1 = *(const float4*)(Ap + (size_t)64 * NHD + k0);
        float4 w0 = *(const float4*)(Wp0 + k0);
        float4 w1 = *(const float4*)(Wp1 + k0);

        __syncthreads();
        As[lk + 0][lr]      = a0.x; As[lk + 1][lr]      = a0.y;
        As[lk + 2][lr]      = a0.z; As[lk + 3][lr]      = a0.w;
        As[lk + 0][lr + 64] = a1.x; As[lk + 1][lr + 64] = a1.y;
        As[lk + 2][lr + 64] = a1.z; As[lk + 3][lr + 64] = a1.w;
        Ws[lk + 0][lr]      = w0.x; Ws[lk + 1][lr]      = w0.y;
        Ws[lk + 2][lr]      = w0.z; Ws[lk + 3][lr]      = w0.w;
        Ws[lk + 0][lr + 64] = w1.x; Ws[lk + 1][lr + 64] = w1.y;
        Ws[lk + 2][lr + 64] = w1.z; Ws[lk + 3][lr + 64] = w1.w;
        __syncthreads();

#pragma unroll
        for (int kk = 0; kk < 16; kk++) {
            float av[8], wv[8];
            *(float4*)(av)     = *(const float4*)&As[kk][tm * 8];
            *(float4*)(av + 4) = *(const float4*)&As[kk][tm * 8 + 4];
#pragma unroll
            for (int g = 0; g < 4; g++)
                *(float2*)&wv[g * 2] = *(const float2*)&Ws[kk][g * 32 + tn * 2];
#pragma unroll
            for (int i = 0; i < 8; i++)
#pragma unroll
                for (int j = 0; j < 8; j++)
                    acc[i][j] = fmaf(av[i], wv[j], acc[i][j]);
        }
    }

    // Epilogue: add vt @ w_ih^T + b_ih + b_hh, apply LSTM cell.
    const int h0 = nh0 + tn * 2;
    float addc[4][2], wi0c[4][2], wi1c[4][2];
#pragma unroll
    for (int g = 0; g < 4; g++)
#pragma unroll
        for (int c = 0; c < 2; c++) {
            const int grow = g * NHD + h0 + c;
            addc[g][c] = b_ih[grow] + b_hh[grow];
            wi0c[g][c] = w_ih[grow * 2 + 0];
            wi1c[g][c] = w_ih[grow * 2 + 1];
        }

#pragma unroll
    for (int i = 0; i < 8; i++) {
        const int b  = m0 + tm * 8 + i;
        const float v0 = v[((size_t)t * BATCH + b) * 2 + 0];
        const float v1 = v[((size_t)t * BATCH + b) * 2 + 1];
#pragma unroll
        for (int c = 0; c < 2; c++) {
            float gv[4];
#pragma unroll
            for (int g = 0; g < 4; g++)
                gv[g] = acc[i][g * 2 + c] + addc[g][c]
                      + v0 * wi0c[g][c] + v1 * wi1c[g][c];
            const float ig = 1.f / (1.f + expf(-gv[0]));
            const float fg = 1.f / (1.f + expf(-gv[1]));
            const float gg = tanhf(gv[2]);
            const float og = 1.f / (1.f + expf(-gv[3]));
            const int idx = b * NHD + h0 + c;
            const float cn = fg * cx_in[idx] + ig * gg;
            cx_out[idx] = cn;
            hx_out[idx] = og * tanhf(cn);
        }
    }
}

// ---------------------------------------------------------------------------
// Launch: encoder (hx0, cx0) -> 50 x [lstm_step, g-GEMM] -> decode every 10
// steps as one [10240, 512] GEMM over K=4096.
// ---------------------------------------------------------------------------
extern "C" void kernel_launch(void* const* d_in, const int* in_sizes, int n_in,
                              void* d_out, int out_size)
{
    const float* v      = (const float*)d_in[0];
    const float* p0     = (const float*)d_in[1];
    const float* enc1_w = (const float*)d_in[2];
    const float* enc1_b = (const float*)d_in[3];
    const float* enc2_w = (const float*)d_in[4];
    const float* enc2_b = (const float*)d_in[5];
    const float* w_ih   = (const float*)d_in[6];
    const float* w_hh   = (const float*)d_in[7];
    const float* b_ih   = (const float*)d_in[8];
    const float* b_hh   = (const float*)d_in[9];
    const float* g_w    = (const float*)d_in[10];
    const float* dec_w  = (const float*)d_in[11];
    const float* dec_b  = (const float*)d_in[12];
    float* out = (float*)d_out;

    float *hx, *cx, *gbuf;
    cudaGetSymbolAddress((void**)&hx,   d_hx);
    cudaGetSymbolAddress((void**)&cx,   d_cx);
    cudaGetSymbolAddress((void**)&gbuf, d_gbuf);

    const size_t SZ  = (size_t)BATCH * NHD;
    const size_t GSZ = (size_t)BATCH * NGD;
    const dim3 blk(256);

    // Encoders: hx0 = p0 @ enc1_w^T + b1 ; cx0 = p0 @ enc2_w^T + b2
    gemm_bt<false><<<dim3(NPD / 128, BATCH / 128), blk>>>(
        p0, enc1_w, enc1_b, hx, BATCH, NHD, NPD);
    gemm_bt<false><<<dim3(NPD / 128, BATCH / 128), blk>>>(
        p0, enc2_w, enc2_b, cx, BATCH, NHD, NPD);

    for (int t = 0; t < T_STEPS; t++) {
        const int buf = t & 1;
        lstm_step<<<dim3(NHD / 32, BATCH / 128), blk>>>(
            hx + buf * SZ, cx + buf * SZ,
            hx + (buf ^ 1) * SZ, cx + (buf ^ 1) * SZ,
            v, w_hh, w_ih, b_ih, b_hh, t);

        gemm_bt<true><<<dim3(NGD / 128, BATCH / 128), blk>>>(
            hx + (buf ^ 1) * SZ, g_w, nullptr,
            gbuf + (size_t)(t % CHUNK) * GSZ, BATCH, NGD, NHD);

        if ((t % CHUNK) == CHUNK - 1) {
            const int c0 = t - (CHUNK - 1);
            gemm_bt<false><<<dim3(NPD / 128, (CHUNK * BATCH) / 128), blk>>>(
                gbuf, dec_w, dec_b,
                out + (size_t)c0 * BATCH * NPD,
                CHUNK * BATCH, NPD, NGD);
        }
    }
}

// round 2
// speedup vs baseline: 3.0045x; 3.0045x over previous
#include <cuda_runtime.h>
#include <math.h>
#include <stdint.h>

#define T_STEPS 50
#define BATCH   1024
#define NPD     512
#define NHD     512
#define NGD     4096
#define CHUNK   10

// Device scratch (no cudaMalloc allowed)
__device__ float d_hx[2][BATCH * NHD];
__device__ float d_cx[2][BATCH * NHD];
__device__ float d_gates[(size_t)BATCH * 4 * NHD];            // 8 MB
__device__ float d_gbuf[CHUNK][(size_t)BATCH * NGD];          // 168 MB

// ---------------------------------------------------------------------------
// tf32 tensor-core GEMM:  C[M,N] = A[M,K] @ W[N,K]^T  (+bias) (optional ReLU)
// Block tile 128x128x32, 256 threads, 8 warps of 64x32, mma.m16n8k8.tf32.
// Requires M%128==0, N%128==0, K%32==0 (true for all shapes here).
// Smem: 2 stages x (A 128x36 + W 128x36) floats = 73728 B (dynamic).
// ---------------------------------------------------------------------------
#define SMEM_STRIDE 36
#define STAGE_FLOATS (2 * 128 * SMEM_STRIDE)   // A tile + W tile
#define GEMM_SMEM_BYTES (2 * STAGE_FLOATS * 4)

__device__ __forceinline__ uint32_t f2tf(float x) {
    uint32_t r;
    asm("cvt.rna.tf32.f32 %0, %1;" : "=r"(r) : "f"(x));
    return r;
}

__device__ __forceinline__ void mma_tf32(float* c,
    uint32_t a0, uint32_t a1, uint32_t a2, uint32_t a3,
    uint32_t b0, uint32_t b1)
{
    asm volatile(
        "mma.sync.aligned.m16n8k8.row.col.f32.tf32.tf32.f32 "
        "{%0,%1,%2,%3}, {%4,%5,%6,%7}, {%8,%9}, {%0,%1,%2,%3};"
        : "+f"(c[0]), "+f"(c[1]), "+f"(c[2]), "+f"(c[3])
        : "r"(a0), "r"(a1), "r"(a2), "r"(a3), "r"(b0), "r"(b1));
}

#define CP_ASYNC16(dst_sm, src_gm)                                          \
    asm volatile("cp.async.cg.shared.global [%0], [%1], 16;\n"              \
                 :: "r"(dst_sm), "l"(src_gm))
#define CP_COMMIT() asm volatile("cp.async.commit_group;\n" ::: "memory")
#define CP_WAIT0()  asm volatile("cp.async.wait_group 0;\n" ::: "memory")

template <bool RELU, bool BIAS>
__global__ __launch_bounds__(256)
void gemm_tf32(const float* __restrict__ A, const float* __restrict__ W,
               const float* __restrict__ bias, float* __restrict__ C,
               int M, int N, int K)
{
    extern __shared__ float sm[];

    const int tid  = threadIdx.x;
    const int lane = tid & 31;
    const int wid  = tid >> 5;
    const int g    = lane >> 2;       // 0..7
    const int l4   = lane & 3;        // 0..3
    const int wm   = (wid >> 2) * 64; // warp row offset in block tile
    const int wn   = (wid & 3) * 32;  // warp col offset

    const int m0 = blockIdx.y << 7;
    const int n0 = blockIdx.x << 7;

    // loader mapping: 8 float4 per 32-float row, 32 rows per pass, 4 passes
    const int kq = tid & 7;           // float4 index within row
    const int r0 = tid >> 3;          // 0..31

    float acc[4][4][4];
#pragma unroll
    for (int i = 0; i < 4; i++)
#pragma unroll
        for (int j = 0; j < 4; j++)
#pragma unroll
            for (int e = 0; e < 4; e++) acc[i][j][e] = 0.f;

    const int KT = K >> 5;            // number of 32-wide K tiles

    auto load_tiles = [&](int kt, int stage) {
        float* sA = sm + stage * STAGE_FLOATS;
        float* sW = sA + 128 * SMEM_STRIDE;
        const int k0 = kt << 5;
        const float* Ab = A + (size_t)m0 * K + k0 + kq * 4;
        const float* Wb = W + (size_t)n0 * K + k0 + kq * 4;
#pragma unroll
        for (int i = 0; i < 4; i++) {
            const int r = r0 + 32 * i;
            uint32_t da = (uint32_t)__cvta_generic_to_shared(
                              sA + r * SMEM_STRIDE + kq * 4);
            uint32_t dw = (uint32_t)__cvta_generic_to_shared(
                              sW + r * SMEM_STRIDE + kq * 4);
            CP_ASYNC16(da, Ab + (size_t)r * K);
            CP_ASYNC16(dw, Wb + (size_t)r * K);
        }
        CP_COMMIT();
    };

    load_tiles(0, 0);

    for (int kt = 0; kt < KT; kt++) {
        CP_WAIT0();
        __syncthreads();
        if (kt + 1 < KT) load_tiles(kt + 1, (kt + 1) & 1);

        const float* sA = sm + (kt & 1) * STAGE_FLOATS;
        const float* sW = sA + 128 * SMEM_STRIDE;

#pragma unroll
        for (int ks = 0; ks < 4; ks++) {
            const int kk = ks * 8 + l4;
            uint32_t bfr[4][2];
#pragma unroll
            for (int tj = 0; tj < 4; tj++) {
                const float* bp = sW + (wn + tj * 8 + g) * SMEM_STRIDE + kk;
                bfr[tj][0] = f2tf(bp[0]);
                bfr[tj][1] = f2tf(bp[4]);
            }
#pragma unroll
            for (int ti = 0; ti < 4; ti++) {
                const float* ap = sA + (wm + ti * 16 + g) * SMEM_STRIDE + kk;
                uint32_t a0 = f2tf(ap[0]);
                uint32_t a1 = f2tf(ap[8 * SMEM_STRIDE]);
                uint32_t a2 = f2tf(ap[4]);
                uint32_t a3 = f2tf(ap[8 * SMEM_STRIDE + 4]);
#pragma unroll
                for (int tj = 0; tj < 4; tj++)
                    mma_tf32(acc[ti][tj], a0, a1, a2, a3,
                             bfr[tj][0], bfr[tj][1]);
            }
        }
        __syncthreads();
    }

    // Epilogue
#pragma unroll
    for (int ti = 0; ti < 4; ti++) {
        const int row0 = m0 + wm + ti * 16 + g;
#pragma unroll
        for (int tj = 0; tj < 4; tj++) {
            const int col = n0 + wn + tj * 8 + (l4 << 1);
            float b0 = 0.f, b1 = 0.f;
            if (BIAS) { b0 = bias[col]; b1 = bias[col + 1]; }
            float x0 = acc[ti][tj][0] + b0;
            float x1 = acc[ti][tj][1] + b1;
            float x2 = acc[ti][tj][2] + b0;
            float x3 = acc[ti][tj][3] + b1;
            if (RELU) {
                x0 = fmaxf(x0, 0.f); x1 = fmaxf(x1, 0.f);
                x2 = fmaxf(x2, 0.f); x3 = fmaxf(x3, 0.f);
            }
            *(float2*)(C + (size_t)row0 * N + col)       = make_float2(x0, x1);
            *(float2*)(C + (size_t)(row0 + 8) * N + col) = make_float2(x2, x3);
        }
    }
}

// ---------------------------------------------------------------------------
// LSTM pointwise: gates preactivations (from GEMM) + rank-2 input term +
// biases -> sigmoid/tanh -> cell/hidden update. One thread per (b, h).
// ---------------------------------------------------------------------------
__global__ __launch_bounds__(512)
void lstm_point(const float* __restrict__ gates,
                const float* __restrict__ cx_in,
                float* __restrict__ hx_out, float* __restrict__ cx_out,
                const float* __restrict__ v,
                const float* __restrict__ w_ih,
                const float* __restrict__ b_ih,
                const float* __restrict__ b_hh,
                int t)
{
    const int idx = blockIdx.x * blockDim.x + threadIdx.x;  // 0..B*NH-1
    const int h = idx & (NHD - 1);
    const int b = idx >> 9;

    const float v0 = v[((size_t)t * BATCH + b) * 2 + 0];
    const float v1 = v[((size_t)t * BATCH + b) * 2 + 1];

    float gv[4];
#pragma unroll
    for (int gt = 0; gt < 4; gt++) {
        const int grow = gt * NHD + h;
        gv[gt] = gates[(size_t)b * (4 * NHD) + grow]
               + b_ih[grow] + b_hh[grow]
               + v0 * w_ih[grow * 2 + 0] + v1 * w_ih[grow * 2 + 1];
    }
    const float ig = 1.f / (1.f + expf(-gv[0]));
    const float fg = 1.f / (1.f + expf(-gv[1]));
    const float gg = tanhf(gv[2]);
    const float og = 1.f / (1.f + expf(-gv[3]));

    const float cn = fg * cx_in[idx] + ig * gg;
    cx_out[idx] = cn;
    hx_out[idx] = og * tanhf(cn);
}

// ---------------------------------------------------------------------------
extern "C" void kernel_launch(void* const* d_in, const int* in_sizes, int n_in,
                              void* d_out, int out_size)
{
    const float* v      = (const float*)d_in[0];
    const float* p0     = (const float*)d_in[1];
    const float* enc1_w = (const float*)d_in[2];
    const float* enc1_b = (const float*)d_in[3];
    const float* enc2_w = (const float*)d_in[4];
    const float* enc2_b = (const float*)d_in[5];
    const float* w_ih   = (const float*)d_in[6];
    const float* w_hh   = (const float*)d_in[7];
    const float* b_ih   = (const float*)d_in[8];
    const float* b_hh   = (const float*)d_in[9];
    const float* g_w    = (const float*)d_in[10];
    const float* dec_w  = (const float*)d_in[11];
    const float* dec_b  = (const float*)d_in[12];
    float* out = (float*)d_out;

    float *hx, *cx, *gates, *gbuf;
    cudaGetSymbolAddress((void**)&hx,    d_hx);
    cudaGetSymbolAddress((void**)&cx,    d_cx);
    cudaGetSymbolAddress((void**)&gates, d_gates);
    cudaGetSymbolAddress((void**)&gbuf,  d_gbuf);

    cudaFuncSetAttribute(gemm_tf32<false, true>,
        cudaFuncAttributeMaxDynamicSharedMemorySize, GEMM_SMEM_BYTES);
    cudaFuncSetAttribute(gemm_tf32<false, false>,
        cudaFuncAttributeMaxDynamicSharedMemorySize, GEMM_SMEM_BYTES);
    cudaFuncSetAttribute(gemm_tf32<true, false>,
        cudaFuncAttributeMaxDynamicSharedMemorySize, GEMM_SMEM_BYTES);

    const size_t SZ  = (size_t)BATCH * NHD;
    const size_t GSZ = (size_t)BATCH * NGD;
    const dim3 blk(256);

    // Encoders
    gemm_tf32<false, true><<<dim3(NHD / 128, BATCH / 128), blk, GEMM_SMEM_BYTES>>>(
        p0, enc1_w, enc1_b, hx, BATCH, NHD, NPD);
    gemm_tf32<false, true><<<dim3(NHD / 128, BATCH / 128), blk, GEMM_SMEM_BYTES>>>(
        p0, enc2_w, enc2_b, cx, BATCH, NHD, NPD);

    for (int t = 0; t < T_STEPS; t++) {
        const int buf = t & 1;

        // gates = hx @ w_hh^T   [1024, 2048]
        gemm_tf32<false, false><<<dim3((4 * NHD) / 128, BATCH / 128), blk,
                                  GEMM_SMEM_BYTES>>>(
            hx + buf * SZ, w_hh, nullptr, gates, BATCH, 4 * NHD, NHD);

        // pointwise LSTM cell
        lstm_point<<<(BATCH * NHD) / 512, 512>>>(
            gates, cx + buf * SZ,
            hx + (buf ^ 1) * SZ, cx + (buf ^ 1) * SZ,
            v, w_ih, b_ih, b_hh, t);

        // g = relu(hx @ g_w^T)   [1024, 4096]
        gemm_tf32<true, false><<<dim3(NGD / 128, BATCH / 128), blk,
                                 GEMM_SMEM_BYTES>>>(
            hx + (buf ^ 1) * SZ, g_w, nullptr,
            gbuf + (size_t)(t % CHUNK) * GSZ, BATCH, NGD, NHD);

        // decode every CHUNK steps: [10240, 512] over K=4096
        if ((t % CHUNK) == CHUNK - 1) {
            const int c0 = t - (CHUNK - 1);
            gemm_tf32<false, true><<<dim3(NPD / 128, (CHUNK * BATCH) / 128),
                                     blk, GEMM_SMEM_BYTES>>>(
                gbuf, dec_w, dec_b,
                out + (size_t)c0 * BATCH * NPD,
                CHUNK * BATCH, NPD, NGD);
        }
    }
}

// round 4
// speedup vs baseline: 4.5222x; 1.5052x over previous
#include <cuda_runtime.h>
#include <cuda_fp16.h>
#include <math.h>
#include <stdint.h>

#define T_STEPS 50
#define BATCH   1024
#define NPD     512
#define NHD     512
#define NGD     4096
#define CHUNK   10

// ---------------- device scratch (no cudaMalloc allowed) ----------------
__device__ __half d_hxh[BATCH * NHD];
__device__ float  d_cx[BATCH * NHD];
__device__ __half d_gbufh[(size_t)CHUNK * BATCH * NGD];   // 84 MB
// fp16 operand copies
__device__ __half d_p0h[BATCH * NPD];
__device__ __half d_e1h[NHD * NPD];
__device__ __half d_e2h[NHD * NPD];
__device__ __half d_whhh[4 * NHD * NHD];                  // permuted [h*4+g][k]
__device__ __half d_gwh[(size_t)NGD * NHD];
__device__ __half d_dech[(size_t)NPD * NGD];
__device__ float4 d_bsum4[NHD];                           // per h: b_ih+b_hh, 4 gates
__device__ float4 d_wihp[2 * NHD];                        // per h: 2x float4 (4 gates x 2)

__device__ __forceinline__ uint32_t sm_u32(const void* p) {
    return (uint32_t)__cvta_generic_to_shared(p);
}

#define CP_ASYNC16(dst, src) \
    asm volatile("cp.async.cg.shared.global [%0], [%1], 16;\n" :: "r"(dst), "l"(src))
#define CP_COMMIT() asm volatile("cp.async.commit_group;\n" ::: "memory")
#define CP_WAIT0()  asm volatile("cp.async.wait_group 0;\n" ::: "memory")
#define CP_WAIT1()  asm volatile("cp.async.wait_group 1;\n" ::: "memory")

__device__ __forceinline__ void mma_f16(float* c, uint32_t a0, uint32_t a1,
                                        uint32_t a2, uint32_t a3,
                                        uint32_t b0, uint32_t b1)
{
    asm volatile(
        "mma.sync.aligned.m16n8k16.row.col.f32.f16.f16.f32 "
        "{%0,%1,%2,%3}, {%4,%5,%6,%7}, {%8,%9}, {%0,%1,%2,%3};"
        : "+f"(c[0]), "+f"(c[1]), "+f"(c[2]), "+f"(c[3])
        : "r"(a0), "r"(a1), "r"(a2), "r"(a3), "r"(b0), "r"(b1));
}

// Modes
#define MODE_ENC_H 0   // float out? no: half out + bias (hx0)
#define MODE_ENC_C 1   // float out + bias (cx0)
#define MODE_GATES 2   // fused LSTM cell epilogue (writes hxh + cx)
#define MODE_G     3   // relu, half out
#define MODE_DEC   4   // float out + bias

// ---------------------------------------------------------------------------
// fp16 tensor-core GEMM: C[M,N] = A[M,K] @ W[N,K]^T, block 128x128x32,
// 256 threads, 8 warps (64x32 warp tile), mma.m16n8k16, cp.async double buffer.
// Smem rows padded to 40 halves -> conflict-free .b32 fragment loads.
// ---------------------------------------------------------------------------
template <int MODE>
__global__ __launch_bounds__(256)
void gemm_h(const __half* __restrict__ A, const __half* __restrict__ W,
            const float* __restrict__ bias, void* __restrict__ Cout,
            int M, int N, int K,
            float* __restrict__ cxp, __half* __restrict__ hxp,
            const float* __restrict__ vp, int t)
{
    __shared__ __half sT[2][2][128][40];   // [stage][A/W][row][k] = 40960 B

    const int tid  = threadIdx.x;
    const int lane = tid & 31;
    const int wid  = tid >> 5;
    const int lg   = lane >> 2;            // row group 0..7
    const int l4   = lane & 3;
    const int wm   = (wid >> 2) * 64;
    const int wn   = (wid & 3) * 32;
    const int m0   = blockIdx.y << 7;
    const int n0   = blockIdx.x << 7;

    float acc[4][4][4];
#pragma unroll
    for (int i = 0; i < 4; i++)
#pragma unroll
        for (int j = 0; j < 4; j++)
#pragma unroll
            for (int e = 0; e < 4; e++) acc[i][j][e] = 0.f;

    auto load_stage = [&](int kt, int stage) {
#pragma unroll
        for (int it = 0; it < 4; it++) {
            const int i    = tid + it * 256;
            const int row  = i >> 2;          // 0..255
            const int quad = i & 3;           // 16B quad within 64B row
            const __half* src;
            uint32_t dst;
            if (row < 128) {
                src = A + (size_t)(m0 + row) * K + (kt << 5) + (quad << 3);
                dst = sm_u32(&sT[stage][0][row][quad << 3]);
            } else {
                src = W + (size_t)(n0 + row - 128) * K + (kt << 5) + (quad << 3);
                dst = sm_u32(&sT[stage][1][row - 128][quad << 3]);
            }
            CP_ASYNC16(dst, src);
        }
        CP_COMMIT();
    };

    const int KT = K >> 5;
    load_stage(0, 0);

    for (int kt = 0; kt < KT; kt++) {
        if (kt + 1 < KT) { load_stage(kt + 1, (kt + 1) & 1); CP_WAIT1(); }
        else             { CP_WAIT0(); }
        __syncthreads();

        const int st = kt & 1;
#pragma unroll
        for (int ks = 0; ks < 2; ks++) {
            const int kk = ks * 16 + 2 * l4;
            uint32_t bf[4][2];
#pragma unroll
            for (int tj = 0; tj < 4; tj++) {
                const __half* pb = &sT[st][1][wn + tj * 8 + lg][kk];
                bf[tj][0] = *(const uint32_t*)pb;
                bf[tj][1] = *(const uint32_t*)(pb + 8);
            }
#pragma unroll
            for (int ti = 0; ti < 4; ti++) {
                const __half* pa = &sT[st][0][wm + ti * 16 + lg][kk];
                uint32_t a0 = *(const uint32_t*)pa;
                uint32_t a1 = *(const uint32_t*)(pa + 8 * 40);
                uint32_t a2 = *(const uint32_t*)(pa + 8);
                uint32_t a3 = *(const uint32_t*)(pa + 8 * 40 + 8);
#pragma unroll
                for (int tj = 0; tj < 4; tj++)
                    mma_f16(acc[ti][tj], a0, a1, a2, a3, bf[tj][0], bf[tj][1]);
            }
        }
        __syncthreads();
    }

    // ---------------- epilogues ----------------
    if (MODE == MODE_GATES) {
        const int hbase = (n0 >> 2) + (wn >> 2);
#pragma unroll
        for (int ti = 0; ti < 4; ti++) {
            const int myrow = m0 + wm + ti * 16 + lg + ((l4 & 1) << 3);
            const float2 vv = *(const float2*)(vp + ((size_t)t * BATCH + myrow) * 2);
#pragma unroll
            for (int tj = 0; tj < 4; tj++) {
                const int h = hbase + tj * 2 + (l4 >> 1);
                float* c = acc[ti][tj];
                float2 send = (l4 & 1) ? make_float2(c[0], c[1])
                                       : make_float2(c[2], c[3]);
                float2 recv;
                recv.x = __shfl_xor_sync(0xffffffffu, send.x, 1);
                recv.y = __shfl_xor_sync(0xffffffffu, send.y, 1);
                float g0, g1, g2, g3;
                if (!(l4 & 1)) { g0 = c[0]; g1 = c[1]; g2 = recv.x; g3 = recv.y; }
                else           { g0 = recv.x; g1 = recv.y; g2 = c[2]; g3 = c[3]; }

                const float4 bs = d_bsum4[h];
                const float4 wA = d_wihp[2 * h];
                const float4 wB = d_wihp[2 * h + 1];
                g0 += bs.x + vv.x * wA.x + vv.y * wA.y;
                g1 += bs.y + vv.x * wA.z + vv.y * wA.w;
                g2 += bs.z + vv.x * wB.x + vv.y * wB.y;
                g3 += bs.w + vv.x * wB.z + vv.y * wB.w;

                const float ig = 1.f / (1.f + __expf(-g0));
                const float fg = 1.f / (1.f + __expf(-g1));
                const float gg = tanhf(g2);
                const float og = 1.f / (1.f + __expf(-g3));

                const int idx = myrow * NHD + h;
                const float cn = fg * cxp[idx] + ig * gg;
                cxp[idx] = cn;
                hxp[idx] = __float2half(og * tanhf(cn));
            }
        }
        return;
    }

#pragma unroll
    for (int ti = 0; ti < 4; ti++) {
        const int r0 = m0 + wm + ti * 16 + lg;
#pragma unroll
        for (int tj = 0; tj < 4; tj++) {
            const int col = n0 + wn + tj * 8 + 2 * l4;
            float* c = acc[ti][tj];
            float b0 = 0.f, b1 = 0.f;
            if (MODE == MODE_ENC_H || MODE == MODE_ENC_C || MODE == MODE_DEC) {
                b0 = bias[col]; b1 = bias[col + 1];
            }
            float x0 = c[0] + b0, x1 = c[1] + b1;
            float x2 = c[2] + b0, x3 = c[3] + b1;
            if (MODE == MODE_G) {
                x0 = fmaxf(x0, 0.f); x1 = fmaxf(x1, 0.f);
                x2 = fmaxf(x2, 0.f); x3 = fmaxf(x3, 0.f);
            }
            if (MODE == MODE_ENC_C || MODE == MODE_DEC) {
                float* C = (float*)Cout;
                *(float2*)(C + (size_t)r0 * N + col)       = make_float2(x0, x1);
                *(float2*)(C + (size_t)(r0 + 8) * N + col) = make_float2(x2, x3);
            } else {
                __half* C = (__half*)Cout;
                *(__half2*)(C + (size_t)r0 * N + col) =
                    __floats2half2_rn(x0, x1);
                *(__half2*)(C + (size_t)(r0 + 8) * N + col) =
                    __floats2half2_rn(x2, x3);
            }
        }
    }
}

// ---------------------------------------------------------------------------
// Prep kernels (run once per launch)
// ---------------------------------------------------------------------------
__global__ void f2h4(const float4* __restrict__ s, __half2* __restrict__ d, int n4)
{
    const int i = blockIdx.x * 256 + threadIdx.x;
    if (i < n4) {
        float4 x = s[i];
        d[i * 2]     = __floats2half2_rn(x.x, x.y);
        d[i * 2 + 1] = __floats2half2_rn(x.z, x.w);
    }
}

// permute w_hh rows to [h*4+g][k], fp16, float4-wide over k
__global__ void perm_whh(const float* __restrict__ w, __half2* __restrict__ d)
{
    const int i = blockIdx.x * 256 + threadIdx.x;   // 0 .. 2048*128-1
    const int n = i >> 7;                           // permuted row
    const int q = i & 127;                          // float4 idx within row
    const int src = ((n & 3) << 9) + (n >> 2);      // g*512 + h
    const float4 x = *(const float4*)(w + (size_t)src * NHD + (q << 2));
    d[(size_t)n * (NHD / 2) + q * 2]     = __floats2half2_rn(x.x, x.y);
    d[(size_t)n * (NHD / 2) + q * 2 + 1] = __floats2half2_rn(x.z, x.w);
}

__global__ void prep_hb(const float* __restrict__ bi, const float* __restrict__ bh,
                        const float* __restrict__ wih)
{
    const int h = blockIdx.x * 256 + threadIdx.x;
    if (h < NHD) {
        d_bsum4[h] = make_float4(bi[h] + bh[h],
                                 bi[NHD + h] + bh[NHD + h],
                                 bi[2 * NHD + h] + bh[2 * NHD + h],
                                 bi[3 * NHD + h] + bh[3 * NHD + h]);
        d_wihp[2 * h] = make_float4(wih[h * 2], wih[h * 2 + 1],
                                    wih[(NHD + h) * 2], wih[(NHD + h) * 2 + 1]);
        d_wihp[2 * h + 1] = make_float4(wih[(2 * NHD + h) * 2], wih[(2 * NHD + h) * 2 + 1],
                                        wih[(3 * NHD + h) * 2], wih[(3 * NHD + h) * 2 + 1]);
    }
}

// ---------------------------------------------------------------------------
extern "C" void kernel_launch(void* const* d_in, const int* in_sizes, int n_in,
                              void* d_out, int out_size)
{
    const float* v      = (const float*)d_in[0];
    const float* p0     = (const float*)d_in[1];
    const float* enc1_w = (const float*)d_in[2];
    const float* enc1_b = (const float*)d_in[3];
    const float* enc2_w = (const float*)d_in[4];
    const float* enc2_b = (const float*)d_in[5];
    const float* w_ih   = (const float*)d_in[6];
    const float* w_hh   = (const float*)d_in[7];
    const float* b_ih   = (const float*)d_in[8];
    const float* b_hh   = (const float*)d_in[9];
    const float* g_w    = (const float*)d_in[10];
    const float* dec_w  = (const float*)d_in[11];
    const float* dec_b  = (const float*)d_in[12];
    float* out = (float*)d_out;

    __half *hxh, *gbufh, *p0h, *e1h, *e2h, *whhh, *gwh, *dech;
    float* cx;
    cudaGetSymbolAddress((void**)&hxh,   d_hxh);
    cudaGetSymbolAddress((void**)&cx,    d_cx);
    cudaGetSymbolAddress((void**)&gbufh, d_gbufh);
    cudaGetSymbolAddress((void**)&p0h,   d_p0h);
    cudaGetSymbolAddress((void**)&e1h,   d_e1h);
    cudaGetSymbolAddress((void**)&e2h,   d_e2h);
    cudaGetSymbolAddress((void**)&whhh,  d_whhh);
    cudaGetSymbolAddress((void**)&gwh,   d_gwh);
    cudaGetSymbolAddress((void**)&dech,  d_dech);

    // operand conversion (once per launch)
    f2h4<<<(BATCH * NPD / 4 + 255) / 256, 256>>>((const float4*)p0, (__half2*)p0h, BATCH * NPD / 4);
    f2h4<<<(NHD * NPD / 4 + 255) / 256, 256>>>((const float4*)enc1_w, (__half2*)e1h, NHD * NPD / 4);
    f2h4<<<(NHD * NPD / 4 + 255) / 256, 256>>>((const float4*)enc2_w, (__half2*)e2h, NHD * NPD / 4);
    f2h4<<<((int)(NGD * NHD / 4) + 255) / 256, 256>>>((const float4*)g_w, (__half2*)gwh, NGD * NHD / 4);
    f2h4<<<((int)(NPD * NGD / 4) + 255) / 256, 256>>>((const float4*)dec_w, (__half2*)dech, NPD * NGD / 4);
    perm_whh<<<(4 * NHD * NHD / 4) / 256, 256>>>(w_hh, (__half2*)whhh);
    prep_hb<<<2, 256>>>(b_ih, b_hh, w_ih);

    const dim3 blk(256);

    // encoders
    gemm_h<MODE_ENC_H><<<dim3(NHD / 128, BATCH / 128), blk>>>(
        p0h, e1h, enc1_b, hxh, BATCH, NHD, NPD, nullptr, nullptr, nullptr, 0);
    gemm_h<MODE_ENC_C><<<dim3(NHD / 128, BATCH / 128), blk>>>(
        p0h, e2h, enc2_b, cx, BATCH, NHD, NPD, nullptr, nullptr, nullptr, 0);

    for (int t = 0; t < T_STEPS; t++) {
        // fused gates GEMM + LSTM cell: updates hxh, cx in place
        gemm_h<MODE_GATES><<<dim3((4 * NHD) / 128, BATCH / 128), blk>>>(
            hxh, whhh, nullptr, nullptr, BATCH, 4 * NHD, NHD, cx, hxh, v, t);

        // g = relu(hx @ g_w^T) -> fp16
        gemm_h<MODE_G><<<dim3(NGD / 128, BATCH / 128), blk>>>(
            hxh, gwh, nullptr, gbufh + (size_t)(t % CHUNK) * BATCH * NGD,
            BATCH, NGD, NHD, nullptr, nullptr, nullptr, 0);

        // decode chunk: [10240, 512] over K=4096
        if ((t % CHUNK) == CHUNK - 1) {
            const int c0 = t - (CHUNK - 1);
            gemm_h<MODE_DEC><<<dim3(NPD / 128, (CHUNK * BATCH) / 128), blk>>>(
                gbufh, dech, dec_b, out + (size_t)c0 * BATCH * NPD,
                CHUNK * BATCH, NPD, NGD, nullptr, nullptr, nullptr, 0);
        }
    }
}

// round 5
// speedup vs baseline: 4.6050x; 1.0183x over previous
#include <cuda_runtime.h>
#include <cuda_fp16.h>
#include <math.h>
#include <stdint.h>

#define T_STEPS 50
#define BATCH   1024
#define NPD     512
#define NHD     512
#define NGD     4096
#define RING    8

// ---------------- device scratch (no cudaMalloc allowed) ----------------
__device__ __half d_hxh[2][BATCH * NHD];
__device__ float  d_cx[BATCH * NHD];
__device__ __half d_gbufh[RING][(size_t)BATCH * NGD];     // 64 MB ring
__device__ __half d_p0h[BATCH * NPD];
__device__ __half d_e1h[NHD * NPD];
__device__ __half d_e2h[NHD * NPD];
__device__ __half d_whhh[4 * NHD * NHD];                  // permuted [h*4+g][k]
__device__ __half d_gwh[(size_t)NGD * NHD];
__device__ __half d_dech[(size_t)NPD * NGD];
__device__ float4 d_bsum4[NHD];
__device__ float4 d_wihp[2 * NHD];

__device__ __forceinline__ uint32_t sm_u32(const void* p) {
    return (uint32_t)__cvta_generic_to_shared(p);
}

#define CP_ASYNC16(dst, src) \
    asm volatile("cp.async.cg.shared.global [%0], [%1], 16;\n" :: "r"(dst), "l"(src))
#define CP_COMMIT() asm volatile("cp.async.commit_group;\n" ::: "memory")
#define CP_WAIT0()  asm volatile("cp.async.wait_group 0;\n" ::: "memory")
#define CP_WAIT1()  asm volatile("cp.async.wait_group 1;\n" ::: "memory")

__device__ __forceinline__ void mma_f16(float* c, uint32_t a0, uint32_t a1,
                                        uint32_t a2, uint32_t a3,
                                        uint32_t b0, uint32_t b1)
{
    asm volatile(
        "mma.sync.aligned.m16n8k16.row.col.f32.f16.f16.f32 "
        "{%0,%1,%2,%3}, {%4,%5,%6,%7}, {%8,%9}, {%0,%1,%2,%3};"
        : "+f"(c[0]), "+f"(c[1]), "+f"(c[2]), "+f"(c[3])
        : "r"(a0), "r"(a1), "r"(a2), "r"(a3), "r"(b0), "r"(b1));
}

#define MODE_ENC_H 0
#define MODE_ENC_C 1
#define MODE_GATES 2
#define MODE_G     3
#define MODE_TAIL  4

// ---------------------------------------------------------------------------
// Mega kernel: every CTA computes a 128x128x512 fp16 GEMM tile.
//  - blockIdx.x < primN : primary task (encoder / gates / g) per MODE.
//  - otherwise          : a decode K-slice (kc of step td), accumulated into
//                         out with strict graph-ordered RMW (deterministic).
// Launch index L: decode slice kc of step t is carried by launch L=2t+2+kc.
// ---------------------------------------------------------------------------
template <int MODE>
__global__ void __launch_bounds__(256, 2)
mega(const __half* __restrict__ A, const __half* __restrict__ W,
     const float* __restrict__ bias, void* __restrict__ Cout,
     float* __restrict__ out, const float* __restrict__ dec_b,
     const float* __restrict__ vp, float* __restrict__ cxp,
     __half* __restrict__ hxp, int t, int L, int primN)
{
    constexpr int N = (MODE == MODE_GATES) ? 2048 : (MODE == MODE_G) ? 4096 : 512;
    __shared__ __half sT[2][2][128][40];

    const int tid  = threadIdx.x;
    const int lane = tid & 31;
    const int wid  = tid >> 5;
    const int lg   = lane >> 2;
    const int l4   = lane & 3;
    const int wm   = (wid >> 2) * 64;
    const int wn   = (wid & 3) * 32;

    const int  bx   = blockIdx.x;
    const bool prim = (MODE != MODE_TAIL) && (bx < primN);

    const __half *Ab, *Wb;
    int lda, ldw, m0, n0, td = 0, kc = 0;

    if (prim) {
        constexpr int NT = N / 128;
        n0 = (bx % NT) << 7;
        m0 = (bx / NT) << 7;
        lda = 512; ldw = 512;
        Ab = A + (size_t)m0 * 512;
        Wb = W + (size_t)n0 * 512;
    } else {
        const int s     = (MODE == MODE_TAIL) ? bx : (bx - primN);
        const int slice = s >> 5;
        const int tile  = s & 31;
        kc = 2 * slice + (L & 1);
        const int num = L - 2 - kc;
        if (num < 0) return;
        td = num >> 1;
        if (td >= T_STEPS) return;
        m0 = (tile >> 2) << 7;
        n0 = (tile & 3) << 7;
        lda = NGD; ldw = NGD;
        Ab = &d_gbufh[td & (RING - 1)][0] + (size_t)m0 * NGD + kc * 512;
        Wb = d_dech + (size_t)n0 * NGD + kc * 512;
    }

    float acc[4][4][4];
#pragma unroll
    for (int i = 0; i < 4; i++)
#pragma unroll
        for (int j = 0; j < 4; j++)
#pragma unroll
            for (int e = 0; e < 4; e++) acc[i][j][e] = 0.f;

    auto load_stage = [&](int kt, int stage) {
#pragma unroll
        for (int it = 0; it < 4; it++) {
            const int i    = tid + it * 256;
            const int row  = i >> 2;
            const int quad = i & 3;
            const __half* src = (row < 128)
                ? Ab + (size_t)row * lda + (kt << 5) + (quad << 3)
                : Wb + (size_t)(row - 128) * ldw + (kt << 5) + (quad << 3);
            const uint32_t dst = (row < 128)
                ? sm_u32(&sT[stage][0][row][quad << 3])
                : sm_u32(&sT[stage][1][row - 128][quad << 3]);
            CP_ASYNC16(dst, src);
        }
        CP_COMMIT();
    };

    load_stage(0, 0);
#pragma unroll 1
    for (int kt = 0; kt < 16; kt++) {
        if (kt + 1 < 16) { load_stage(kt + 1, (kt + 1) & 1); CP_WAIT1(); }
        else             { CP_WAIT0(); }
        __syncthreads();

        const int st = kt & 1;
#pragma unroll
        for (int ks = 0; ks < 2; ks++) {
            const int kk = ks * 16 + 2 * l4;
            uint32_t bf[4][2];
#pragma unroll
            for (int tj = 0; tj < 4; tj++) {
                const __half* pb = &sT[st][1][wn + tj * 8 + lg][kk];
                bf[tj][0] = *(const uint32_t*)pb;
                bf[tj][1] = *(const uint32_t*)(pb + 8);
            }
#pragma unroll
            for (int ti = 0; ti < 4; ti++) {
                const __half* pa = &sT[st][0][wm + ti * 16 + lg][kk];
                uint32_t a0 = *(const uint32_t*)pa;
                uint32_t a1 = *(const uint32_t*)(pa + 8 * 40);
                uint32_t a2 = *(const uint32_t*)(pa + 8);
                uint32_t a3 = *(const uint32_t*)(pa + 8 * 40 + 8);
#pragma unroll
                for (int tj = 0; tj < 4; tj++)
                    mma_f16(acc[ti][tj], a0, a1, a2, a3, bf[tj][0], bf[tj][1]);
            }
        }
        __syncthreads();
    }

    // ---------------- decode (secondary) epilogue ----------------
    if (!prim) {
        float* ob = out + (size_t)td * BATCH * NPD;
#pragma unroll
        for (int ti = 0; ti < 4; ti++) {
            const int r0 = m0 + wm + ti * 16 + lg;
#pragma unroll
            for (int tj = 0; tj < 4; tj++) {
                const int col = n0 + wn + tj * 8 + 2 * l4;
                float* c = acc[ti][tj];
                float* p = ob + (size_t)r0 * NPD + col;
                float* q = ob + (size_t)(r0 + 8) * NPD + col;
                if (kc == 0) {
                    const float b0 = dec_b[col], b1 = dec_b[col + 1];
                    *(float2*)p = make_float2(c[0] + b0, c[1] + b1);
                    *(float2*)q = make_float2(c[2] + b0, c[3] + b1);
                } else {
                    const float2 o0 = *(float2*)p, o1 = *(float2*)q;
                    *(float2*)p = make_float2(o0.x + c[0], o0.y + c[1]);
                    *(float2*)q = make_float2(o1.x + c[2], o1.y + c[3]);
                }
            }
        }
        return;
    }

    // ---------------- primary epilogues ----------------
    if (MODE == MODE_GATES) {
        const int hbase = (n0 >> 2) + (wn >> 2);
#pragma unroll
        for (int ti = 0; ti < 4; ti++) {
            const int myrow = m0 + wm + ti * 16 + lg + ((l4 & 1) << 3);
            const float2 vv = *(const float2*)(vp + ((size_t)t * BATCH + myrow) * 2);
#pragma unroll
            for (int tj = 0; tj < 4; tj++) {
                const int h = hbase + tj * 2 + (l4 >> 1);
                float* c = acc[ti][tj];
                float2 send = (l4 & 1) ? make_float2(c[0], c[1])
                                       : make_float2(c[2], c[3]);
                float2 recv;
                recv.x = __shfl_xor_sync(0xffffffffu, send.x, 1);
                recv.y = __shfl_xor_sync(0xffffffffu, send.y, 1);
                float g0, g1, g2, g3;
                if (!(l4 & 1)) { g0 = c[0]; g1 = c[1]; g2 = recv.x; g3 = recv.y; }
                else           { g0 = recv.x; g1 = recv.y; g2 = c[2]; g3 = c[3]; }

                const float4 bs = d_bsum4[h];
                const float4 wA = d_wihp[2 * h];
                const float4 wB = d_wihp[2 * h + 1];
                g0 += bs.x + vv.x * wA.x + vv.y * wA.y;
                g1 += bs.y + vv.x * wA.z + vv.y * wA.w;
                g2 += bs.z + vv.x * wB.x + vv.y * wB.y;
                g3 += bs.w + vv.x * wB.z + vv.y * wB.w;

                const float ig = 1.f / (1.f + __expf(-g0));
                const float fg = 1.f / (1.f + __expf(-g1));
                const float gg = tanhf(g2);
                const float og = 1.f / (1.f + __expf(-g3));

                const int idx = myrow * NHD + h;
                const float cn = fg * cxp[idx] + ig * gg;
                cxp[idx] = cn;
                hxp[idx] = __float2half(og * tanhf(cn));
            }
        }
        return;
    }

#pragma unroll
    for (int ti = 0; ti < 4; ti++) {
        const int r0 = m0 + wm + ti * 16 + lg;
#pragma unroll
        for (int tj = 0; tj < 4; tj++) {
            const int col = n0 + wn + tj * 8 + 2 * l4;
            float* c = acc[ti][tj];
            float b0 = 0.f, b1 = 0.f;
            if (MODE == MODE_ENC_H || MODE == MODE_ENC_C) {
                b0 = bias[col]; b1 = bias[col + 1];
            }
            float x0 = c[0] + b0, x1 = c[1] + b1;
            float x2 = c[2] + b0, x3 = c[3] + b1;
            if (MODE == MODE_G) {
                x0 = fmaxf(x0, 0.f); x1 = fmaxf(x1, 0.f);
                x2 = fmaxf(x2, 0.f); x3 = fmaxf(x3, 0.f);
            }
            if (MODE == MODE_ENC_C) {
                float* C = (float*)Cout;
                *(float2*)(C + (size_t)r0 * N + col)       = make_float2(x0, x1);
                *(float2*)(C + (size_t)(r0 + 8) * N + col) = make_float2(x2, x3);
            } else {
                __half* C = (__half*)Cout;
                *(__half2*)(C + (size_t)r0 * N + col)       = __floats2half2_rn(x0, x1);
                *(__half2*)(C + (size_t)(r0 + 8) * N + col) = __floats2half2_rn(x2, x3);
            }
        }
    }
}

// ---------------------------------------------------------------------------
// Prep kernels
// ---------------------------------------------------------------------------
__global__ void f2h4(const float4* __restrict__ s, __half2* __restrict__ d, int n4)
{
    const int i = blockIdx.x * 256 + threadIdx.x;
    if (i < n4) {
        float4 x = s[i];
        d[i * 2]     = __floats2half2_rn(x.x, x.y);
        d[i * 2 + 1] = __floats2half2_rn(x.z, x.w);
    }
}

__global__ void perm_whh(const float* __restrict__ w, __half2* __restrict__ d)
{
    const int i = blockIdx.x * 256 + threadIdx.x;
    const int n = i >> 7;
    const int q = i & 127;
    const int src = ((n & 3) << 9) + (n >> 2);
    const float4 x = *(const float4*)(w + (size_t)src * NHD + (q << 2));
    d[(size_t)n * (NHD / 2) + q * 2]     = __floats2half2_rn(x.x, x.y);
    d[(size_t)n * (NHD / 2) + q * 2 + 1] = __floats2half2_rn(x.z, x.w);
}

__global__ void prep_hb(const float* __restrict__ bi, const float* __restrict__ bh,
                        const float* __restrict__ wih)
{
    const int h = blockIdx.x * 256 + threadIdx.x;
    if (h < NHD) {
        d_bsum4[h] = make_float4(bi[h] + bh[h],
                                 bi[NHD + h] + bh[NHD + h],
                                 bi[2 * NHD + h] + bh[2 * NHD + h],
                                 bi[3 * NHD + h] + bh[3 * NHD + h]);
        d_wihp[2 * h] = make_float4(wih[h * 2], wih[h * 2 + 1],
                                    wih[(NHD + h) * 2], wih[(NHD + h) * 2 + 1]);
        d_wihp[2 * h + 1] = make_float4(wih[(2 * NHD + h) * 2], wih[(2 * NHD + h) * 2 + 1],
                                        wih[(3 * NHD + h) * 2], wih[(3 * NHD + h) * 2 + 1]);
    }
}

// ---------------------------------------------------------------------------
extern "C" void kernel_launch(void* const* d_in, const int* in_sizes, int n_in,
                              void* d_out, int out_size)
{
    const float* v      = (const float*)d_in[0];
    const float* p0     = (const float*)d_in[1];
    const float* enc1_w = (const float*)d_in[2];
    const float* enc1_b = (const float*)d_in[3];
    const float* enc2_w = (const float*)d_in[4];
    const float* enc2_b = (const float*)d_in[5];
    const float* w_ih   = (const float*)d_in[6];
    const float* w_hh   = (const float*)d_in[7];
    const float* b_ih   = (const float*)d_in[8];
    const float* b_hh   = (const float*)d_in[9];
    const float* g_w    = (const float*)d_in[10];
    const float* dec_w  = (const float*)d_in[11];
    const float* dec_b  = (const float*)d_in[12];
    float* out = (float*)d_out;

    __half *hxh, *gbufh, *p0h, *e1h, *e2h, *whhh, *gwh, *dech;
    float* cx;
    cudaGetSymbolAddress((void**)&hxh,   d_hxh);
    cudaGetSymbolAddress((void**)&cx,    d_cx);
    cudaGetSymbolAddress((void**)&gbufh, d_gbufh);
    cudaGetSymbolAddress((void**)&p0h,   d_p0h);
    cudaGetSymbolAddress((void**)&e1h,   d_e1h);
    cudaGetSymbolAddress((void**)&e2h,   d_e2h);
    cudaGetSymbolAddress((void**)&whhh,  d_whhh);
    cudaGetSymbolAddress((void**)&gwh,   d_gwh);
    cudaGetSymbolAddress((void**)&dech,  d_dech);

    // operand conversion (once per launch)
    f2h4<<<(BATCH * NPD / 4 + 255) / 256, 256>>>((const float4*)p0, (__half2*)p0h, BATCH * NPD / 4);
    f2h4<<<(NHD * NPD / 4 + 255) / 256, 256>>>((const float4*)enc1_w, (__half2*)e1h, NHD * NPD / 4);
    f2h4<<<(NHD * NPD / 4 + 255) / 256, 256>>>((const float4*)enc2_w, (__half2*)e2h, NHD * NPD / 4);
    f2h4<<<((int)(NGD * NHD / 4) + 255) / 256, 256>>>((const float4*)g_w, (__half2*)gwh, NGD * NHD / 4);
    f2h4<<<((int)(NPD * NGD / 4) + 255) / 256, 256>>>((const float4*)dec_w, (__half2*)dech, NPD * NGD / 4);
    perm_whh<<<(4 * NHD * NHD / 4) / 256, 256>>>(w_hh, (__half2*)whhh);
    prep_hb<<<2, 256>>>(b_ih, b_hh, w_ih);

    const size_t SZ = (size_t)BATCH * NHD;

    // encoders (no piggyback; L=-1 keeps secondary path inert via primN=grid)
    mega<MODE_ENC_H><<<32, 256>>>(p0h, e1h, enc1_b, hxh, out, dec_b,
                                  nullptr, nullptr, nullptr, 0, -100, 32);
    mega<MODE_ENC_C><<<32, 256>>>(p0h, e2h, enc2_b, cx, out, dec_b,
                                  nullptr, nullptr, nullptr, 0, -100, 32);

    for (int t = 0; t < T_STEPS; t++) {
        const int cur = t & 1, nxt = cur ^ 1;

        // gates GEMM + fused LSTM cell (+4 decode slices)
        mega<MODE_GATES><<<128 + 128, 256>>>(
            hxh + cur * SZ, whhh, nullptr, nullptr, out, dec_b,
            v, cx, hxh + nxt * SZ, t, 2 * t, 128);

        // g = relu(hx @ g_w^T) -> fp16 ring slot (+4 decode slices)
        mega<MODE_G><<<256 + 128, 256>>>(
            hxh + nxt * SZ, gwh, nullptr,
            gbufh + (size_t)(t & (RING - 1)) * BATCH * NGD, out, dec_b,
            nullptr, nullptr, nullptr, t, 2 * t + 1, 256);
    }

    // decode tails: launches L = 100..107 finish steps 46..49
    for (int L = 2 * T_STEPS; L < 2 * T_STEPS + 8; L++) {
        mega<MODE_TAIL><<<128, 256>>>(
            nullptr, nullptr, nullptr, nullptr, out, dec_b,
            nullptr, nullptr, nullptr, 0, L, 0);
    }
}

// round 6
// speedup vs baseline: 5.5631x; 1.2081x over previous
#include <cuda_runtime.h>
#include <cuda_fp16.h>
#include <math.h>
#include <stdint.h>

#define T_STEPS 50
#define BATCH   1024
#define NPD     512
#define NHD     512
#define NGD     4096
#define RING    16

// ---------------- device scratch (no cudaMalloc allowed) ----------------
__device__ __half d_hxh[2][BATCH * NHD];
__device__ float  d_cx[BATCH * NHD];
__device__ __half d_gbufh[RING][(size_t)BATCH * NGD];     // 128 MB ring
__device__ __half d_p0h[BATCH * NPD];
__device__ __half d_e1h[NHD * NPD];
__device__ __half d_e2h[NHD * NPD];
__device__ __half d_whhh[4 * NHD * NHD];                  // permuted [h*4+g][k]
__device__ __half d_gwh[(size_t)NGD * NHD];
__device__ __half d_dech[(size_t)NPD * NGD];
__device__ float4 d_bsum4[NHD];
__device__ float4 d_wihp[2 * NHD];
__device__ float  d_encb1[NHD];
__device__ float  d_encb2[NHD];
__device__ float  d_decb[NPD];

__device__ __forceinline__ uint32_t sm_u32(const void* p) {
    return (uint32_t)__cvta_generic_to_shared(p);
}

#define CP_ASYNC16(dst, src) \
    asm volatile("cp.async.cg.shared.global [%0], [%1], 16;\n" :: "r"(dst), "l"(src))
#define CP_COMMIT() asm volatile("cp.async.commit_group;\n" ::: "memory")
#define CP_WAIT0()  asm volatile("cp.async.wait_group 0;\n" ::: "memory")

#define LDSM_X4(r0, r1, r2, r3, addr) \
    asm volatile("ldmatrix.sync.aligned.m8n8.x4.shared.b16 {%0,%1,%2,%3}, [%4];" \
                 : "=r"(r0), "=r"(r1), "=r"(r2), "=r"(r3) : "r"(addr))

__device__ __forceinline__ void mma_f16(float* c, uint32_t a0, uint32_t a1,
                                        uint32_t a2, uint32_t a3,
                                        uint32_t b0, uint32_t b1)
{
    asm volatile(
        "mma.sync.aligned.m16n8k16.row.col.f32.f16.f16.f32 "
        "{%0,%1,%2,%3}, {%4,%5,%6,%7}, {%8,%9}, {%0,%1,%2,%3};"
        : "+f"(c[0]), "+f"(c[1]), "+f"(c[2]), "+f"(c[3])
        : "r"(a0), "r"(a1), "r"(a2), "r"(a3), "r"(b0), "r"(b1));
}

// roles
#define R_GATES 0
#define R_G     1
#define R_DEC   2
#define R_ENCH  3
#define R_ENCC  4

// ---------------------------------------------------------------------------
// Mega kernel: one launch per LSTM step. 640 CTAs, each a 128x128x512 fp16
// GEMM tile:
//   bx [0,128)   : gates(t=L)  (fused LSTM cell epilogue)
//   bx [128,384) : g(t=L-1)    (relu, fp16 ring-slot out)
//   bx [384,640) : decode K-slice kc of step td=L-2-kc, ordered RMW into out
// L=-1: encoder launch (64 CTAs: 32 ENC_H + 32 ENC_C).
// ---------------------------------------------------------------------------
__global__ void __launch_bounds__(256, 2)
mega(int L, float* __restrict__ out, const float* __restrict__ vp)
{
    __shared__ __half sT[2][256][40];   // [stage][row: 0-127 A, 128-255 W][k]

    const int tid  = threadIdx.x;
    const int lane = tid & 31;
    const int wid  = tid >> 5;
    const int lg   = lane >> 2;
    const int l4   = lane & 3;
    const int wm   = (wid >> 2) * 64;
    const int wn   = (wid & 3) * 32;
    const int bx   = blockIdx.x;

    int role, m0, n0, td = 0, kc = 0, lda;
    const __half *Ab, *Wb;

    if (L < 0) {
        role = (bx < 32) ? R_ENCH : R_ENCC;
        const int s = bx & 31;
        m0 = (s >> 2) << 7; n0 = (s & 3) << 7;
        Ab = d_p0h + (size_t)m0 * NPD;
        Wb = ((role == R_ENCH) ? d_e1h : d_e2h) + (size_t)n0 * NPD;
        lda = 512;
    } else if (bx < 128) {
        if (L >= T_STEPS) return;
        role = R_GATES;
        n0 = (bx & 15) << 7; m0 = (bx >> 4) << 7;
        Ab = &d_hxh[L & 1][0] + (size_t)m0 * NHD;
        Wb = d_whhh + (size_t)n0 * NHD;
        lda = 512;
    } else if (bx < 384) {
        if (L < 1 || L > T_STEPS) return;
        role = R_G;
        const int s = bx - 128;
        n0 = (s & 31) << 7; m0 = (s >> 5) << 7;
        Ab = &d_hxh[L & 1][0] + (size_t)m0 * NHD;
        Wb = d_gwh + (size_t)n0 * NHD;
        lda = 512;
    } else {
        const int s = bx - 384;
        kc = s >> 5;
        const int tile = s & 31;
        td = L - 2 - kc;
        if (td < 0 || td >= T_STEPS) return;
        role = R_DEC;
        m0 = (tile >> 2) << 7; n0 = (tile & 3) << 7;
        Ab = &d_gbufh[td & (RING - 1)][0] + (size_t)m0 * NGD + kc * 512;
        Wb = d_dech + (size_t)n0 * NGD + kc * 512;
        lda = NGD;
    }

    float acc[4][4][4];
#pragma unroll
    for (int i = 0; i < 4; i++)
#pragma unroll
        for (int j = 0; j < 4; j++)
#pragma unroll
            for (int e = 0; e < 4; e++) acc[i][j][e] = 0.f;

    auto load_stage = [&](int kt, int stage) {
#pragma unroll
        for (int it = 0; it < 4; it++) {
            const int i    = tid + it * 256;
            const int row  = i >> 2;
            const int quad = i & 3;
            const __half* src =
                ((row < 128) ? Ab + (size_t)row * lda
                             : Wb + (size_t)(row - 128) * lda)
                + (kt << 5) + (quad << 3);
            CP_ASYNC16(sm_u32(&sT[stage][row][quad << 3]), src);
        }
        CP_COMMIT();
    };

    // ldmatrix lane addresses (stage 0; add stage/ks byte offsets per use)
    uint32_t aAdr[4], bAdr[2];
#pragma unroll
    for (int ti = 0; ti < 4; ti++)
        aAdr[ti] = sm_u32(&sT[0][wm + ti * 16 + (lane & 15)][(lane >> 4) << 3]);
#pragma unroll
    for (int p = 0; p < 2; p++)
        bAdr[p] = sm_u32(&sT[0][128 + wn + p * 16 + ((lane >> 4) << 3) + (lane & 7)]
                             [((lane >> 3) & 1) << 3]);

    constexpr uint32_t STAGE_B = 256 * 40 * 2;   // 20480

    load_stage(0, 0);
#pragma unroll 1
    for (int kt = 0; kt < 16; kt++) {
        CP_WAIT0();
        __syncthreads();
        if (kt + 1 < 16) load_stage(kt + 1, (kt + 1) & 1);

        const uint32_t so = (kt & 1) * STAGE_B;
#pragma unroll
        for (int ks = 0; ks < 2; ks++) {
            const uint32_t ko = so + ks * 32;
            uint32_t af[4][4], bf[2][4];
#pragma unroll
            for (int p = 0; p < 2; p++)
                LDSM_X4(bf[p][0], bf[p][1], bf[p][2], bf[p][3], bAdr[p] + ko);
#pragma unroll
            for (int ti = 0; ti < 4; ti++)
                LDSM_X4(af[ti][0], af[ti][1], af[ti][2], af[ti][3], aAdr[ti] + ko);
#pragma unroll
            for (int ti = 0; ti < 4; ti++)
#pragma unroll
                for (int tj = 0; tj < 4; tj++)
                    mma_f16(acc[ti][tj],
                            af[ti][0], af[ti][1], af[ti][2], af[ti][3],
                            bf[tj >> 1][(tj & 1) * 2],
                            bf[tj >> 1][(tj & 1) * 2 + 1]);
        }
    }

    // ---------------- epilogues ----------------
    if (role == R_DEC) {
        float* ob = out + (size_t)td * BATCH * NPD;
#pragma unroll
        for (int ti = 0; ti < 4; ti++) {
            const int r0 = m0 + wm + ti * 16 + lg;
#pragma unroll
            for (int tj = 0; tj < 4; tj++) {
                const int col = n0 + wn + tj * 8 + 2 * l4;
                float* c = acc[ti][tj];
                float* p = ob + (size_t)r0 * NPD + col;
                float* q = ob + (size_t)(r0 + 8) * NPD + col;
                if (kc == 0) {
                    const float b0 = d_decb[col], b1 = d_decb[col + 1];
                    *(float2*)p = make_float2(c[0] + b0, c[1] + b1);
                    *(float2*)q = make_float2(c[2] + b0, c[3] + b1);
                } else {
                    const float2 o0 = *(float2*)p, o1 = *(float2*)q;
                    *(float2*)p = make_float2(o0.x + c[0], o0.y + c[1]);
                    *(float2*)q = make_float2(o1.x + c[2], o1.y + c[3]);
                }
            }
        }
        return;
    }

    if (role == R_GATES) {
        float*  cxp = d_cx;
        __half* hxp = &d_hxh[(L + 1) & 1][0];
        const int hbase = (n0 >> 2) + (wn >> 2);
#pragma unroll
        for (int ti = 0; ti < 4; ti++) {
            const int myrow = m0 + wm + ti * 16 + lg + ((l4 & 1) << 3);
            const float2 vv = *(const float2*)(vp + ((size_t)L * BATCH + myrow) * 2);
#pragma unroll
            for (int tj = 0; tj < 4; tj++) {
                const int h = hbase + tj * 2 + (l4 >> 1);
                float* c = acc[ti][tj];
                float2 send = (l4 & 1) ? make_float2(c[0], c[1])
                                       : make_float2(c[2], c[3]);
                float2 recv;
                recv.x = __shfl_xor_sync(0xffffffffu, send.x, 1);
                recv.y = __shfl_xor_sync(0xffffffffu, send.y, 1);
                float g0, g1, g2, g3;
                if (!(l4 & 1)) { g0 = c[0]; g1 = c[1]; g2 = recv.x; g3 = recv.y; }
                else           { g0 = recv.x; g1 = recv.y; g2 = c[2]; g3 = c[3]; }

                const float4 bs = d_bsum4[h];
                const float4 wA = d_wihp[2 * h];
                const float4 wB = d_wihp[2 * h + 1];
                g0 += bs.x + vv.x * wA.x + vv.y * wA.y;
                g1 += bs.y + vv.x * wA.z + vv.y * wA.w;
                g2 += bs.z + vv.x * wB.x + vv.y * wB.y;
                g3 += bs.w + vv.x * wB.z + vv.y * wB.w;

                const float ig = 1.f / (1.f + __expf(-g0));
                const float fg = 1.f / (1.f + __expf(-g1));
                const float gg = tanhf(g2);
                const float og = 1.f / (1.f + __expf(-g3));

                const int idx = myrow * NHD + h;
                const float cn = fg * cxp[idx] + ig * gg;
                cxp[idx] = cn;
                hxp[idx] = __float2half(og * tanhf(cn));
            }
        }
        return;
    }

    // R_G / R_ENCH: fp16 out (+relu for G); R_ENCC: fp32 out + bias
    const int N = (role == R_G) ? NGD : NHD;
    __half* Ch = (role == R_G) ? &d_gbufh[(L - 1) & (RING - 1)][0]
                               : &d_hxh[0][0];
#pragma unroll
    for (int ti = 0; ti < 4; ti++) {
        const int r0 = m0 + wm + ti * 16 + lg;
#pragma unroll
        for (int tj = 0; tj < 4; tj++) {
            const int col = n0 + wn + tj * 8 + 2 * l4;
            float* c = acc[ti][tj];
            float b0 = 0.f, b1 = 0.f;
            if (role == R_ENCH) { b0 = d_encb1[col]; b1 = d_encb1[col + 1]; }
            if (role == R_ENCC) { b0 = d_encb2[col]; b1 = d_encb2[col + 1]; }
            float x0 = c[0] + b0, x1 = c[1] + b1;
            float x2 = c[2] + b0, x3 = c[3] + b1;
            if (role == R_G) {
                x0 = fmaxf(x0, 0.f); x1 = fmaxf(x1, 0.f);
                x2 = fmaxf(x2, 0.f); x3 = fmaxf(x3, 0.f);
            }
            if (role == R_ENCC) {
                *(float2*)(d_cx + (size_t)r0 * N + col)       = make_float2(x0, x1);
                *(float2*)(d_cx + (size_t)(r0 + 8) * N + col) = make_float2(x2, x3);
            } else {
                *(__half2*)(Ch + (size_t)r0 * N + col)       = __floats2half2_rn(x0, x1);
                *(__half2*)(Ch + (size_t)(r0 + 8) * N + col) = __floats2half2_rn(x2, x3);
            }
        }
    }
}

// ---------------------------------------------------------------------------
// Prep kernels (once per launch)
// ---------------------------------------------------------------------------
__global__ void f2h4(const float4* __restrict__ s, __half2* __restrict__ d, int n4)
{
    const int i = blockIdx.x * 256 + threadIdx.x;
    if (i < n4) {
        float4 x = s[i];
        d[i * 2]     = __floats2half2_rn(x.x, x.y);
        d[i * 2 + 1] = __floats2half2_rn(x.z, x.w);
    }
}

__global__ void perm_whh(const float* __restrict__ w, __half2* __restrict__ d)
{
    const int i = blockIdx.x * 256 + threadIdx.x;
    const int n = i >> 7;
    const int q = i & 127;
    const int src = ((n & 3) << 9) + (n >> 2);
    const float4 x = *(const float4*)(w + (size_t)src * NHD + (q << 2));
    d[(size_t)n * (NHD / 2) + q * 2]     = __floats2half2_rn(x.x, x.y);
    d[(size_t)n * (NHD / 2) + q * 2 + 1] = __floats2half2_rn(x.z, x.w);
}

__global__ void prep_hb(const float* __restrict__ bi, const float* __restrict__ bh,
                        const float* __restrict__ wih,
                        const float* __restrict__ e1b, const float* __restrict__ e2b,
                        const float* __restrict__ db)
{
    const int h = blockIdx.x * 256 + threadIdx.x;
    if (h < NHD) {
        d_bsum4[h] = make_float4(bi[h] + bh[h],
                                 bi[NHD + h] + bh[NHD + h],
                                 bi[2 * NHD + h] + bh[2 * NHD + h],
                                 bi[3 * NHD + h] + bh[3 * NHD + h]);
        d_wihp[2 * h] = make_float4(wih[h * 2], wih[h * 2 + 1],
                                    wih[(NHD + h) * 2], wih[(NHD + h) * 2 + 1]);
        d_wihp[2 * h + 1] = make_float4(wih[(2 * NHD + h) * 2], wih[(2 * NHD + h) * 2 + 1],
                                        wih[(3 * NHD + h) * 2], wih[(3 * NHD + h) * 2 + 1]);
        d_encb1[h] = e1b[h];
        d_encb2[h] = e2b[h];
        d_decb[h]  = db[h];
    }
}

// ---------------------------------------------------------------------------
extern "C" void kernel_launch(void* const* d_in, const int* in_sizes, int n_in,
                              void* d_out, int out_size)
{
    const float* v      = (const float*)d_in[0];
    const float* p0     = (const float*)d_in[1];
    const float* enc1_w = (const float*)d_in[2];
    const float* enc1_b = (const float*)d_in[3];
    const float* enc2_w = (const float*)d_in[4];
    const float* enc2_b = (const float*)d_in[5];
    const float* w_ih   = (const float*)d_in[6];
    const float* w_hh   = (const float*)d_in[7];
    const float* b_ih   = (const float*)d_in[8];
    const float* b_hh   = (const float*)d_in[9];
    const float* g_w    = (const float*)d_in[10];
    const float* dec_w  = (const float*)d_in[11];
    const float* dec_b  = (const float*)d_in[12];
    float* out = (float*)d_out;

    __half *p0h, *e1h, *e2h, *gwh, *dech;
    cudaGetSymbolAddress((void**)&p0h,  d_p0h);
    cudaGetSymbolAddress((void**)&e1h,  d_e1h);
    cudaGetSymbolAddress((void**)&e2h,  d_e2h);
    cudaGetSymbolAddress((void**)&gwh,  d_gwh);
    cudaGetSymbolAddress((void**)&dech, d_dech);
    __half* whhh;
    cudaGetSymbolAddress((void**)&whhh, d_whhh);

    // operand conversion (once per launch)
    f2h4<<<(BATCH * NPD / 4 + 255) / 256, 256>>>((const float4*)p0, (__half2*)p0h, BATCH * NPD / 4);
    f2h4<<<(NHD * NPD / 4 + 255) / 256, 256>>>((const float4*)enc1_w, (__half2*)e1h, NHD * NPD / 4);
    f2h4<<<(NHD * NPD / 4 + 255) / 256, 256>>>((const float4*)enc2_w, (__half2*)e2h, NHD * NPD / 4);
    f2h4<<<((int)(NGD * NHD / 4) + 255) / 256, 256>>>((const float4*)g_w, (__half2*)gwh, NGD * NHD / 4);
    f2h4<<<((int)(NPD * NGD / 4) + 255) / 256, 256>>>((const float4*)dec_w, (__half2*)dech, NPD * NGD / 4);
    perm_whh<<<(4 * NHD * NHD / 4) / 256, 256>>>(w_hh, (__half2*)whhh);
    prep_hb<<<2, 256>>>(b_ih, b_hh, w_ih, enc1_b, enc2_b, dec_b);

    // encoders (hx0 fp16, cx0 fp32)
    mega<<<64, 256>>>(-1, out, v);

    // one launch per step; decode slices ride along; tail finishes decode
    for (int L = 0; L <= T_STEPS + 8; L++)
        mega<<<640, 256>>>(L, out, v);
}